// round 12
// baseline (speedup 1.0000x reference)
#include <cuda_runtime.h>
#include <cuda_bf16.h>
#include <cstdint>

#define BATCH 256
#define TSTEPS 250
#define NIN 700
#define NHID 512
#define NOUT 20
#define VPITCH 720            // per-variant padded K (mult of 48/4)
#define KPAD (4*VPITCH)       // 2880
#define MROWS (BATCH*TSTEPS)  // 64000

// ---------------- device scratch (no allocations allowed) -------------------
__device__ float g_iin[(size_t)MROWS * NHID];
__device__ float g_wrecT[(size_t)NHID * NHID];
__device__ __nv_bfloat16 g_Ahi[(size_t)MROWS * KPAD];
__device__ __nv_bfloat16 g_Alo[(size_t)MROWS * KPAD];
__device__ __nv_bfloat16 g_Bhi[(size_t)NHID * KPAD];
__device__ __nv_bfloat16 g_Blo[(size_t)NHID * KPAD];

// ---------------- prep kernels ----------------------------------------------
__global__ void prep_A(const float* __restrict__ x) {
    int idx = blockIdx.x * blockDim.x + threadIdx.x;      // over MROWS * 180
    if (idx >= MROWS * (VPITCH / 4)) return;
    int m = idx / (VPITCH / 4);
    int k = (idx % (VPITCH / 4)) * 4;
    const float* xr = x + (size_t)m * NIN;
    float a[4];
#pragma unroll
    for (int j = 0; j < 4; j++) a[j] = (k + j < NIN) ? xr[k + j] : 0.f;

    size_t base = (size_t)m * KPAD + k;
#pragma unroll
    for (int v = 0; v < 4; v++) {
        union { __nv_bfloat16 b[4]; uint2 u; } ph, pl;
#pragma unroll
        for (int j = 0; j < 4; j++) {
            float t1 = fminf(fabsf(a[j]), 1.f);
            float val = (v == 0) ? a[j] : (v == 1) ? t1 : (v == 2) ? t1 * t1 : t1 * t1 * t1;
            __nv_bfloat16 h = __float2bfloat16_rn(val);
            ph.b[j] = h;
            pl.b[j] = __float2bfloat16_rn(val - __bfloat162float(h));
        }
        *(uint2*)&g_Ahi[base + (size_t)v * VPITCH] = ph.u;
        *(uint2*)&g_Alo[base + (size_t)v * VPITCH] = pl.u;
    }
}

__global__ void prep_B(const float* __restrict__ wkan, const float* __restrict__ d1,
                       const float* __restrict__ d2, const float* __restrict__ d3) {
    int idx = blockIdx.x * blockDim.x + threadIdx.x;      // over NHID * 180
    if (idx >= NHID * (VPITCH / 4)) return;
    int h = idx / (VPITCH / 4);
    int k = (idx % (VPITCH / 4)) * 4;
    size_t base = (size_t)h * KPAD + k;
#pragma unroll
    for (int v = 0; v < 4; v++) {
        const float* w = (v == 0) ? wkan : (v == 1) ? d1 : (v == 2) ? d2 : d3;
        union { __nv_bfloat16 b[4]; uint2 u; } ph, pl;
#pragma unroll
        for (int j = 0; j < 4; j++) {
            float val = (k + j < NIN) ? w[h * NIN + k + j] : 0.f;
            __nv_bfloat16 hh = __float2bfloat16_rn(val);
            ph.b[j] = hh;
            pl.b[j] = __float2bfloat16_rn(val - __bfloat162float(hh));
        }
        *(uint2*)&g_Bhi[base + (size_t)v * VPITCH] = ph.u;
        *(uint2*)&g_Blo[base + (size_t)v * VPITCH] = pl.u;
    }
}

__global__ void prep_wrec(const float* __restrict__ wrec) {
    int idx = blockIdx.x * blockDim.x + threadIdx.x;
    if (idx >= NHID * NHID) return;
    int j = idx / NHID;
    int h = idx - j * NHID;
    g_wrecT[idx] = wrec[h * NHID + j];
}

// ---------------- phase 1: mma.sync bf16x3 GEMM (ldmatrix, KC=48) -----------
#define BM 128
#define BN 128
#define KC 48
#define NCHUNK (KPAD / KC)       // 60
#define PITCHB 112               // 96 data + 16 pad -> conflict-free mod 128
#define ABYTES (128 * PITCHB)    // 14336 per array
#define O_AHI 0
#define O_ALO ABYTES
#define O_BHI (2 * ABYTES)
#define O_BLO (3 * ABYTES)
#define STAGE (4 * ABYTES)       // 57344
#define NSTG 2
#define SMEM_BYTES (NSTG * STAGE)   // 114688 (112KB) -> 2 CTAs/SM

__device__ __forceinline__ uint32_t smem_u32(const void* p) {
    uint32_t a;
    asm("{ .reg .u64 t; cvta.to.shared.u64 t, %1; cvt.u32.u64 %0, t; }" : "=r"(a) : "l"(p));
    return a;
}
__device__ __forceinline__ void cpa16(uint32_t s, const void* g) {
    asm volatile("cp.async.cg.shared.global [%0], [%1], 16;" :: "r"(s), "l"(g));
}

#define MMA_BF16(C, A, B) \
    asm volatile("mma.sync.aligned.m16n8k16.row.col.f32.bf16.bf16.f32 " \
                 "{%0,%1,%2,%3}, {%4,%5,%6,%7}, {%8,%9}, {%0,%1,%2,%3};" \
                 : "+f"((C)[0]), "+f"((C)[1]), "+f"((C)[2]), "+f"((C)[3]) \
                 : "r"((A)[0]), "r"((A)[1]), "r"((A)[2]), "r"((A)[3]), \
                   "r"((B)[0]), "r"((B)[1]))

#define LDMX4(r0, r1, r2, r3, addr) \
    asm volatile("ldmatrix.sync.aligned.m8n8.x4.shared.b16 {%0,%1,%2,%3}, [%4];" \
                 : "=r"(r0), "=r"(r1), "=r"(r2), "=r"(r3) : "r"(addr))

__global__ void __launch_bounds__(256, 2) gemm_mma() {
    extern __shared__ char smemc[];
    const uint32_t sb = smem_u32(smemc);
    const int tid = threadIdx.x;
    const int warp = tid >> 5;
    const int lane = tid & 31;
    const int wm = (warp >> 2) * 64;
    const int wn = (warp & 3) * 32;
    const int m0 = blockIdx.y * BM;
    const int n0 = blockIdx.x * BN;

    float acc[4][4][4];
#pragma unroll
    for (int i = 0; i < 4; i++)
#pragma unroll
        for (int j = 0; j < 4; j++)
#pragma unroll
            for (int q = 0; q < 4; q++) acc[i][j][q] = 0.f;

    // ldmatrix per-lane base offsets (bytes within one array)
    const uint32_t a_base =
        (uint32_t)(wm + ((lane >> 3) & 1) * 8 + (lane & 7)) * PITCHB + (lane >> 4) * 16;
    const uint32_t b_base =
        (uint32_t)(wn + ((lane >> 4) & 1) * 8 + (lane & 7)) * PITCHB + ((lane >> 3) & 1) * 16;

    // cp.async mapping: per array 128 rows x 6 chunks of 16B = 768 chunks, 3/thread
    auto load_stage = [&](int s) {
        uint32_t b = sb + (uint32_t)(s & (NSTG - 1)) * STAGE;
        int kk0 = s * KC;
#pragma unroll
        for (int it = 0; it < 3; it++) {
            int i = it * 256 + tid;
            int r = i / 6;
            int c = i - r * 6;              // 16B chunk index, 0..5
            uint32_t so = (uint32_t)(r * PITCHB + c * 16);
            size_t ga = (size_t)(m0 + r) * KPAD + kk0 + c * 8;
            size_t gb = (size_t)(n0 + r) * KPAD + kk0 + c * 8;
            cpa16(b + O_AHI + so, &g_Ahi[ga]);
            cpa16(b + O_ALO + so, &g_Alo[ga]);
            cpa16(b + O_BHI + so, &g_Bhi[gb]);
            cpa16(b + O_BLO + so, &g_Blo[gb]);
        }
        asm volatile("cp.async.commit_group;" ::: "memory");
    };

    load_stage(0);

    for (int ch = 0; ch < NCHUNK; ch++) {
        if (ch + 1 < NCHUNK) {
            load_stage(ch + 1);
            asm volatile("cp.async.wait_group 1;" ::: "memory");
        } else {
            asm volatile("cp.async.wait_group 0;" ::: "memory");
        }
        __syncthreads();

        const uint32_t Sb = sb + (uint32_t)(ch & (NSTG - 1)) * STAGE;

#pragma unroll
        for (int ks = 0; ks < 3; ks++) {
            const uint32_t ko = ks * 32;          // byte offset of this k-step
            uint32_t af[4][4], bh[4][2], bl[4][2];

            LDMX4(bh[0][0], bh[0][1], bh[1][0], bh[1][1], Sb + O_BHI + b_base + ko);
            LDMX4(bh[2][0], bh[2][1], bh[3][0], bh[3][1], Sb + O_BHI + b_base + 16 * PITCHB + ko);
            LDMX4(bl[0][0], bl[0][1], bl[1][0], bl[1][1], Sb + O_BLO + b_base + ko);
            LDMX4(bl[2][0], bl[2][1], bl[3][0], bl[3][1], Sb + O_BLO + b_base + 16 * PITCHB + ko);

            // ---- pass 1: ahi x bhi ----
#pragma unroll
            for (int i = 0; i < 4; i++)
                LDMX4(af[i][0], af[i][1], af[i][2], af[i][3],
                      Sb + O_AHI + a_base + (uint32_t)i * 16 * PITCHB + ko);
#pragma unroll
            for (int i = 0; i < 4; i++)
#pragma unroll
                for (int j = 0; j < 4; j++) MMA_BF16(acc[i][j], af[i], bh[j]);
            // ---- pass 2: ahi x blo ----
#pragma unroll
            for (int i = 0; i < 4; i++)
#pragma unroll
                for (int j = 0; j < 4; j++) MMA_BF16(acc[i][j], af[i], bl[j]);
            // ---- pass 3: alo x bhi (reuse af regs) ----
#pragma unroll
            for (int i = 0; i < 4; i++)
                LDMX4(af[i][0], af[i][1], af[i][2], af[i][3],
                      Sb + O_ALO + a_base + (uint32_t)i * 16 * PITCHB + ko);
#pragma unroll
            for (int i = 0; i < 4; i++)
#pragma unroll
                for (int j = 0; j < 4; j++) MMA_BF16(acc[i][j], af[i], bh[j]);
        }
        __syncthreads();
    }

    // ---- epilogue: frags -> smem bounce -> coalesced gmem ----
    {
        float* sC = (float*)smemc;             // [128][132] = 67.6KB <= 112KB
#pragma unroll
        for (int i = 0; i < 4; i++) {
            int r = wm + i * 16 + (lane >> 2);
#pragma unroll
            for (int j = 0; j < 4; j++) {
                int c = wn + j * 8 + 2 * (lane & 3);
                sC[r * 132 + c]           = acc[i][j][0];
                sC[r * 132 + c + 1]       = acc[i][j][1];
                sC[(r + 8) * 132 + c]     = acc[i][j][2];
                sC[(r + 8) * 132 + c + 1] = acc[i][j][3];
            }
        }
        __syncthreads();
#pragma unroll
        for (int it = 0; it < 16; it++) {
            int i = tid + it * 256;            // 0..4095 float4s
            int r = i >> 5, c4 = (i & 31) * 4;
            float4 v = *(float4*)&sC[r * 132 + c4];
            *(float4*)&g_iin[(size_t)(m0 + r) * NHID + n0 + c4] = v;
        }
    }
}

// ---------------- phase 2: persistent per-batch recurrence (unchanged) ------
__global__ void __launch_bounds__(512) snn_seq(const float* __restrict__ wout,
                                               float* __restrict__ out) {
    __shared__ float s_wout[NOUT * NHID];
    __shared__ float s_sf[NHID];
    __shared__ int   s_list[NHID];
    __shared__ int   s_warpcnt[16];
    __shared__ int   s_cnt;
    __shared__ float s_iout[NOUT];

    const int b = blockIdx.x;
    const int h = threadIdx.x;
    const int warp = h >> 5;
    const int lane = h & 31;

    for (int i = h; i < NOUT * NHID; i += 512) s_wout[i] = wout[i];
    s_sf[h] = 0.f;
    if (h == 0) s_cnt = 0;

    float v1 = 0.f, a1 = 0.f, s_prev = 0.f;
    float v_out = 0.f, acc_out = 0.f;

    __syncthreads();

    const float* iin_b = &g_iin[(size_t)b * TSTEPS * NHID];

    for (int t = 0; t < TSTEPS; t++) {
        float rec = 0.f;
        const int cnt = s_cnt;
        int k = 0;
        for (; k + 4 <= cnt; k += 4) {
            int j0 = s_list[k], j1 = s_list[k + 1], j2 = s_list[k + 2], j3 = s_list[k + 3];
            float w0 = g_wrecT[(size_t)j0 * NHID + h];
            float w1 = g_wrecT[(size_t)j1 * NHID + h];
            float w2 = g_wrecT[(size_t)j2 * NHID + h];
            float w3 = g_wrecT[(size_t)j3 * NHID + h];
            rec += w0 + w1 + w2 + w3;
        }
        for (; k < cnt; k++) rec += g_wrecT[(size_t)s_list[k] * NHID + h];

        const float i1 = iin_b[(size_t)t * NHID + h] + rec;

        v1 = 0.95f * v1 + 0.05f * i1 - 1.0f * s_prev;
        a1 = 0.85f * a1 + 0.15f * s_prev;
        const float thr = 1.0f + 0.05f * a1;
        const float s_new = (v1 > thr) ? 1.f : 0.f;

        const unsigned mask = __ballot_sync(0xffffffffu, s_new > 0.f);

        __syncthreads();

        if (lane == 0) s_warpcnt[warp] = __popc(mask);
        s_sf[h] = s_new;

        __syncthreads();

        int base = 0;
#pragma unroll
        for (int w = 0; w < 16; w++) base += (w < warp) ? s_warpcnt[w] : 0;
        if (s_new > 0.f) {
            int pos = base + __popc(mask & ((1u << lane) - 1u));
            s_list[pos] = h;
        }
        if (h == 0) {
            int tot = 0;
#pragma unroll
            for (int w = 0; w < 16; w++) tot += s_warpcnt[w];
            s_cnt = tot;
        }

        for (int o = warp; o < NOUT; o += 16) {
            float p = 0.f;
            const float* wrow = &s_wout[o * NHID];
#pragma unroll 4
            for (int i = lane; i < NHID; i += 32) p += s_sf[i] * wrow[i];
#pragma unroll
            for (int off = 16; off > 0; off >>= 1)
                p += __shfl_down_sync(0xffffffffu, p, off);
            if (lane == 0) s_iout[o] = p;
        }

        __syncthreads();

        if (h < NOUT) {
            v_out = 0.9f * v_out + s_iout[h];
            const float s_o = (v_out > 1.0f) ? 1.f : 0.f;
            v_out = v_out - 1.0f * s_o;
            acc_out += v_out;
        }

        s_prev = s_new;
    }

    if (h < NOUT) out[b * NOUT + h] = acc_out * (1.0f / (float)TSTEPS);
}

// ---------------- launch -----------------------------------------------------
extern "C" void kernel_launch(void* const* d_in, const int* in_sizes, int n_in,
                              void* d_out, int out_size) {
    const float* x    = (const float*)d_in[0];
    const float* wkan = (const float*)d_in[1];
    const float* d1   = (const float*)d_in[2];
    const float* d2   = (const float*)d_in[3];
    const float* d3   = (const float*)d_in[4];
    const float* wrec = (const float*)d_in[5];
    const float* wout = (const float*)d_in[6];
    float* out = (float*)d_out;

    cudaFuncSetAttribute(gemm_mma, cudaFuncAttributeMaxDynamicSharedMemorySize, SMEM_BYTES);

    prep_A<<<(MROWS * (VPITCH / 4) + 255) / 256, 256>>>(x);
    prep_B<<<(NHID * (VPITCH / 4) + 255) / 256, 256>>>(wkan, d1, d2, d3);
    prep_wrec<<<(NHID * NHID + 255) / 256, 256>>>(wrec);

    dim3 grid(NHID / BN, MROWS / BM);   // (4, 500)
    gemm_mma<<<grid, 256, SMEM_BYTES>>>();

    snn_seq<<<BATCH, 512>>>(wout, out);
}

// round 14
// speedup vs baseline: 1.2471x; 1.2471x over previous
#include <cuda_runtime.h>
#include <cuda_bf16.h>
#include <cstdint>

#define BATCH 256
#define TSTEPS 250
#define NIN 700
#define NHID 512
#define NOUT 20
#define VPITCH 704            // per-variant padded K
#define KPAD (4*VPITCH)       // 2816
#define MROWS (BATCH*TSTEPS)  // 64000

// ---------------- device scratch (no allocations allowed) -------------------
__device__ float g_iin[(size_t)MROWS * NHID];
__device__ float g_wrecT[(size_t)NHID * NHID];
__device__ __nv_bfloat16 g_Ahi[(size_t)MROWS * KPAD];
__device__ __nv_bfloat16 g_Alo[(size_t)MROWS * KPAD];
__device__ __nv_bfloat16 g_Bhi[(size_t)NHID * KPAD];
__device__ __nv_bfloat16 g_Blo[(size_t)NHID * KPAD];

// ---------------- prep kernels ----------------------------------------------
__global__ void prep_A(const float* __restrict__ x) {
    int idx = blockIdx.x * blockDim.x + threadIdx.x;      // over MROWS * 176
    if (idx >= MROWS * (VPITCH / 4)) return;
    int m = idx / (VPITCH / 4);
    int k = (idx % (VPITCH / 4)) * 4;
    const float* xr = x + (size_t)m * NIN;
    float a[4];
#pragma unroll
    for (int j = 0; j < 4; j++) a[j] = (k + j < NIN) ? xr[k + j] : 0.f;

    size_t base = (size_t)m * KPAD + k;
#pragma unroll
    for (int v = 0; v < 4; v++) {
        union { __nv_bfloat16 b[4]; uint2 u; } ph, pl;
#pragma unroll
        for (int j = 0; j < 4; j++) {
            float t1 = fminf(fabsf(a[j]), 1.f);
            float val = (v == 0) ? a[j] : (v == 1) ? t1 : (v == 2) ? t1 * t1 : t1 * t1 * t1;
            __nv_bfloat16 h = __float2bfloat16_rn(val);
            ph.b[j] = h;
            pl.b[j] = __float2bfloat16_rn(val - __bfloat162float(h));
        }
        *(uint2*)&g_Ahi[base + (size_t)v * VPITCH] = ph.u;
        *(uint2*)&g_Alo[base + (size_t)v * VPITCH] = pl.u;
    }
}

__global__ void prep_B(const float* __restrict__ wkan, const float* __restrict__ d1,
                       const float* __restrict__ d2, const float* __restrict__ d3) {
    int idx = blockIdx.x * blockDim.x + threadIdx.x;      // over NHID * 176
    if (idx >= NHID * (VPITCH / 4)) return;
    int h = idx / (VPITCH / 4);
    int k = (idx % (VPITCH / 4)) * 4;
    size_t base = (size_t)h * KPAD + k;
#pragma unroll
    for (int v = 0; v < 4; v++) {
        const float* w = (v == 0) ? wkan : (v == 1) ? d1 : (v == 2) ? d2 : d3;
        union { __nv_bfloat16 b[4]; uint2 u; } ph, pl;
#pragma unroll
        for (int j = 0; j < 4; j++) {
            float val = (k + j < NIN) ? w[h * NIN + k + j] : 0.f;
            __nv_bfloat16 hh = __float2bfloat16_rn(val);
            ph.b[j] = hh;
            pl.b[j] = __float2bfloat16_rn(val - __bfloat162float(hh));
        }
        *(uint2*)&g_Bhi[base + (size_t)v * VPITCH] = ph.u;
        *(uint2*)&g_Blo[base + (size_t)v * VPITCH] = pl.u;
    }
}

__global__ void prep_wrec(const float* __restrict__ wrec) {
    int idx = blockIdx.x * blockDim.x + threadIdx.x;
    if (idx >= NHID * NHID) return;
    int j = idx / NHID;
    int h = idx - j * NHID;
    g_wrecT[idx] = wrec[h * NHID + j];
}

// ---------------- phase 1: mma.sync bf16x3 GEMM -----------------------------
// 128x64 tiles, 4 warps, KC=32, swizzled pitch-64 smem, 2 stages = 48KB,
// 4 CTAs/SM.
#define BM 128
#define BN 64
#define KC 32
#define NCHUNK (KPAD / KC)       // 88
// swizzled row: 64 bytes (4 chunks of 16B), phys chunk = c ^ ((r>>1)&3)
#define O_AHI 0
#define O_ALO 8192
#define O_BHI 16384
#define O_BLO 20480
#define STAGE 24576
#define NSTG 2
#define SMEM_BYTES (NSTG * STAGE)   // 49152

__device__ __forceinline__ uint32_t smem_u32(const void* p) {
    uint32_t a;
    asm("{ .reg .u64 t; cvta.to.shared.u64 t, %1; cvt.u32.u64 %0, t; }" : "=r"(a) : "l"(p));
    return a;
}
__device__ __forceinline__ void cpa16(uint32_t s, const void* g) {
    asm volatile("cp.async.cg.shared.global [%0], [%1], 16;" :: "r"(s), "l"(g));
}

#define MMA_BF16(C, A, B) \
    asm volatile("mma.sync.aligned.m16n8k16.row.col.f32.bf16.bf16.f32 " \
                 "{%0,%1,%2,%3}, {%4,%5,%6,%7}, {%8,%9}, {%0,%1,%2,%3};" \
                 : "+f"((C)[0]), "+f"((C)[1]), "+f"((C)[2]), "+f"((C)[3]) \
                 : "r"((A)[0]), "r"((A)[1]), "r"((A)[2]), "r"((A)[3]), \
                   "r"((B)[0]), "r"((B)[1]))

#define LDMX4(r0, r1, r2, r3, addr) \
    asm volatile("ldmatrix.sync.aligned.m8n8.x4.shared.b16 {%0,%1,%2,%3}, [%4];" \
                 : "=r"(r0), "=r"(r1), "=r"(r2), "=r"(r3) : "r"(addr))

__global__ void __launch_bounds__(128, 4) gemm_mma() {
    extern __shared__ char smemc[];
    const uint32_t sb = smem_u32(smemc);
    const int tid = threadIdx.x;
    const int warp = tid >> 5;
    const int lane = tid & 31;
    const int wm = (warp >> 1) * 64;      // 0 / 64
    const int wn = (warp & 1) * 32;       // 0 / 32
    const int m0 = blockIdx.y * BM;
    const int n0 = blockIdx.x * BN;

    float acc[4][4][4];
#pragma unroll
    for (int i = 0; i < 4; i++)
#pragma unroll
        for (int j = 0; j < 4; j++)
#pragma unroll
            for (int q = 0; q < 4; q++) acc[i][j][q] = 0.f;

    // ---- ldmatrix per-lane addressing (swizzled) ----
    // A: rows wm + ((lane>>3)&1)*8 + (lane&7), chunk-half cb = lane>>4
    const int ra = wm + ((lane >> 3) & 1) * 8 + (lane & 7);
    const int cba = lane >> 4;                       // 0/1
    const int sa = (ra >> 1) & 3;
    const uint32_t a_row = (uint32_t)ra * 64;
    const uint32_t a_c0 = (uint32_t)((cba ^ sa) << 4);          // ks=0
    const uint32_t a_c1 = (uint32_t)(((cba + 2) ^ sa) << 4);    // ks=1
    // B: rows wn + ((lane>>4)&1)*8 + (lane&7), chunk-half cb = (lane>>3)&1
    const int rb = wn + ((lane >> 4) & 1) * 8 + (lane & 7);
    const int cbb = (lane >> 3) & 1;
    const int sbx = (rb >> 1) & 3;
    const uint32_t b_row = (uint32_t)rb * 64;
    const uint32_t b_c0 = (uint32_t)((cbb ^ sbx) << 4);
    const uint32_t b_c1 = (uint32_t)(((cbb + 2) ^ sbx) << 4);

    // ---- cp.async stage loader ----
    auto load_stage = [&](int s) {
        uint32_t b = sb + (uint32_t)(s & (NSTG - 1)) * STAGE;
        int kk0 = s * KC;
        // A arrays: 128 rows x 4 chunks = 512 chunks, 4 iters
#pragma unroll
        for (int it = 0; it < 4; it++) {
            int i = it * 128 + tid;
            int r = i >> 2, c = i & 3;
            uint32_t so = (uint32_t)(r * 64 + ((c ^ ((r >> 1) & 3)) << 4));
            size_t ga = (size_t)(m0 + r) * KPAD + kk0 + c * 8;
            cpa16(b + O_AHI + so, &g_Ahi[ga]);
            cpa16(b + O_ALO + so, &g_Alo[ga]);
        }
        // B arrays: 64 rows x 4 chunks = 256 chunks, 2 iters
#pragma unroll
        for (int it = 0; it < 2; it++) {
            int i = it * 128 + tid;
            int r = i >> 2, c = i & 3;
            uint32_t so = (uint32_t)(r * 64 + ((c ^ ((r >> 1) & 3)) << 4));
            size_t gb = (size_t)(n0 + r) * KPAD + kk0 + c * 8;
            cpa16(b + O_BHI + so, &g_Bhi[gb]);
            cpa16(b + O_BLO + so, &g_Blo[gb]);
        }
        asm volatile("cp.async.commit_group;" ::: "memory");
    };

    load_stage(0);

    for (int ch = 0; ch < NCHUNK; ch++) {
        if (ch + 1 < NCHUNK) {
            load_stage(ch + 1);
            asm volatile("cp.async.wait_group 1;" ::: "memory");
        } else {
            asm volatile("cp.async.wait_group 0;" ::: "memory");
        }
        __syncthreads();

        const uint32_t Sb = sb + (uint32_t)(ch & (NSTG - 1)) * STAGE;

#pragma unroll
        for (int ks = 0; ks < 2; ks++) {
            const uint32_t aco = ks ? a_c1 : a_c0;
            const uint32_t bco = ks ? b_c1 : b_c0;
            uint32_t af[4][4], bh[4][2], bl[4][2];

            LDMX4(bh[0][0], bh[0][1], bh[1][0], bh[1][1], Sb + O_BHI + b_row + bco);
            LDMX4(bh[2][0], bh[2][1], bh[3][0], bh[3][1], Sb + O_BHI + b_row + 1024 + bco);
            LDMX4(bl[0][0], bl[0][1], bl[1][0], bl[1][1], Sb + O_BLO + b_row + bco);
            LDMX4(bl[2][0], bl[2][1], bl[3][0], bl[3][1], Sb + O_BLO + b_row + 1024 + bco);

            // ---- pass 1: ahi x bhi ----
#pragma unroll
            for (int i = 0; i < 4; i++)
                LDMX4(af[i][0], af[i][1], af[i][2], af[i][3],
                      Sb + O_AHI + a_row + (uint32_t)i * 1024 + aco);
#pragma unroll
            for (int i = 0; i < 4; i++)
#pragma unroll
                for (int j = 0; j < 4; j++) MMA_BF16(acc[i][j], af[i], bh[j]);
            // ---- pass 2: ahi x blo ----
#pragma unroll
            for (int i = 0; i < 4; i++)
#pragma unroll
                for (int j = 0; j < 4; j++) MMA_BF16(acc[i][j], af[i], bl[j]);
            // ---- pass 3: alo x bhi (reuse af regs) ----
#pragma unroll
            for (int i = 0; i < 4; i++)
                LDMX4(af[i][0], af[i][1], af[i][2], af[i][3],
                      Sb + O_ALO + a_row + (uint32_t)i * 1024 + aco);
#pragma unroll
            for (int i = 0; i < 4; i++)
#pragma unroll
                for (int j = 0; j < 4; j++) MMA_BF16(acc[i][j], af[i], bh[j]);
        }
        __syncthreads();
    }

    // ---- epilogue: frags -> smem bounce -> coalesced gmem ----
    {
        float* sC = (float*)smemc;             // [128][68] = 34.8KB
#pragma unroll
        for (int i = 0; i < 4; i++) {
            int r = wm + i * 16 + (lane >> 2);
#pragma unroll
            for (int j = 0; j < 4; j++) {
                int c = wn + j * 8 + 2 * (lane & 3);
                sC[r * 68 + c]           = acc[i][j][0];
                sC[r * 68 + c + 1]       = acc[i][j][1];
                sC[(r + 8) * 68 + c]     = acc[i][j][2];
                sC[(r + 8) * 68 + c + 1] = acc[i][j][3];
            }
        }
        __syncthreads();
#pragma unroll
        for (int it = 0; it < 16; it++) {
            int i = tid + it * 128;            // 0..2047 float4s
            int r = i >> 4, c4 = (i & 15) * 4;
            float4 v = *(float4*)&sC[r * 68 + c4];
            *(float4*)&g_iin[(size_t)(m0 + r) * NHID + n0 + c4] = v;
        }
    }
}

// ---------------- phase 2: persistent per-batch recurrence (unchanged) ------
__global__ void __launch_bounds__(512) snn_seq(const float* __restrict__ wout,
                                               float* __restrict__ out) {
    __shared__ float s_wout[NOUT * NHID];
    __shared__ float s_sf[NHID];
    __shared__ int   s_list[NHID];
    __shared__ int   s_warpcnt[16];
    __shared__ int   s_cnt;
    __shared__ float s_iout[NOUT];

    const int b = blockIdx.x;
    const int h = threadIdx.x;
    const int warp = h >> 5;
    const int lane = h & 31;

    for (int i = h; i < NOUT * NHID; i += 512) s_wout[i] = wout[i];
    s_sf[h] = 0.f;
    if (h == 0) s_cnt = 0;

    float v1 = 0.f, a1 = 0.f, s_prev = 0.f;
    float v_out = 0.f, acc_out = 0.f;

    __syncthreads();

    const float* iin_b = &g_iin[(size_t)b * TSTEPS * NHID];

    for (int t = 0; t < TSTEPS; t++) {
        float rec = 0.f;
        const int cnt = s_cnt;
        int k = 0;
        for (; k + 4 <= cnt; k += 4) {
            int j0 = s_list[k], j1 = s_list[k + 1], j2 = s_list[k + 2], j3 = s_list[k + 3];
            float w0 = g_wrecT[(size_t)j0 * NHID + h];
            float w1 = g_wrecT[(size_t)j1 * NHID + h];
            float w2 = g_wrecT[(size_t)j2 * NHID + h];
            float w3 = g_wrecT[(size_t)j3 * NHID + h];
            rec += w0 + w1 + w2 + w3;
        }
        for (; k < cnt; k++) rec += g_wrecT[(size_t)s_list[k] * NHID + h];

        const float i1 = iin_b[(size_t)t * NHID + h] + rec;

        v1 = 0.95f * v1 + 0.05f * i1 - 1.0f * s_prev;
        a1 = 0.85f * a1 + 0.15f * s_prev;
        const float thr = 1.0f + 0.05f * a1;
        const float s_new = (v1 > thr) ? 1.f : 0.f;

        const unsigned mask = __ballot_sync(0xffffffffu, s_new > 0.f);

        __syncthreads();

        if (lane == 0) s_warpcnt[warp] = __popc(mask);
        s_sf[h] = s_new;

        __syncthreads();

        int base = 0;
#pragma unroll
        for (int w = 0; w < 16; w++) base += (w < warp) ? s_warpcnt[w] : 0;
        if (s_new > 0.f) {
            int pos = base + __popc(mask & ((1u << lane) - 1u));
            s_list[pos] = h;
        }
        if (h == 0) {
            int tot = 0;
#pragma unroll
            for (int w = 0; w < 16; w++) tot += s_warpcnt[w];
            s_cnt = tot;
        }

        for (int o = warp; o < NOUT; o += 16) {
            float p = 0.f;
            const float* wrow = &s_wout[o * NHID];
#pragma unroll 4
            for (int i = lane; i < NHID; i += 32) p += s_sf[i] * wrow[i];
#pragma unroll
            for (int off = 16; off > 0; off >>= 1)
                p += __shfl_down_sync(0xffffffffu, p, off);
            if (lane == 0) s_iout[o] = p;
        }

        __syncthreads();

        if (h < NOUT) {
            v_out = 0.9f * v_out + s_iout[h];
            const float s_o = (v_out > 1.0f) ? 1.f : 0.f;
            v_out = v_out - 1.0f * s_o;
            acc_out += v_out;
        }

        s_prev = s_new;
    }

    if (h < NOUT) out[b * NOUT + h] = acc_out * (1.0f / (float)TSTEPS);
}

// ---------------- launch -----------------------------------------------------
extern "C" void kernel_launch(void* const* d_in, const int* in_sizes, int n_in,
                              void* d_out, int out_size) {
    const float* x    = (const float*)d_in[0];
    const float* wkan = (const float*)d_in[1];
    const float* d1   = (const float*)d_in[2];
    const float* d2   = (const float*)d_in[3];
    const float* d3   = (const float*)d_in[4];
    const float* wrec = (const float*)d_in[5];
    const float* wout = (const float*)d_in[6];
    float* out = (float*)d_out;

    cudaFuncSetAttribute(gemm_mma, cudaFuncAttributeMaxDynamicSharedMemorySize, SMEM_BYTES);

    prep_A<<<(MROWS * (VPITCH / 4) + 255) / 256, 256>>>(x);
    prep_B<<<(NHID * (VPITCH / 4) + 255) / 256, 256>>>(wkan, d1, d2, d3);
    prep_wrec<<<(NHID * NHID + 255) / 256, 256>>>(wrec);

    dim3 grid(NHID / BN, MROWS / BM);   // (8, 500)
    gemm_mma<<<grid, 128, SMEM_BYTES>>>();

    snn_seq<<<BATCH, 512>>>(wout, out);
}

// round 15
// speedup vs baseline: 1.2486x; 1.0012x over previous
#include <cuda_runtime.h>
#include <cuda_bf16.h>
#include <cstdint>

#define BATCH 256
#define TSTEPS 250
#define NIN 700
#define NHID 512
#define NOUT 20
#define VPITCH 704            // per-variant padded K
#define KPAD (4*VPITCH)       // 2816
#define MROWS (BATCH*TSTEPS)  // 64000

// ---------------- device scratch (no allocations allowed) -------------------
__device__ float g_iin[(size_t)MROWS * NHID];
__device__ float g_wrecT[(size_t)NHID * NHID];
__device__ __nv_bfloat16 g_Ahi[(size_t)MROWS * KPAD];
__device__ __nv_bfloat16 g_Alo[(size_t)MROWS * KPAD];
__device__ __nv_bfloat16 g_Bhi[(size_t)NHID * KPAD];
__device__ __nv_bfloat16 g_Blo[(size_t)NHID * KPAD];

// ---------------- prep kernels ----------------------------------------------
__global__ void prep_A(const float* __restrict__ x) {
    int idx = blockIdx.x * blockDim.x + threadIdx.x;      // over MROWS * 176
    if (idx >= MROWS * (VPITCH / 4)) return;
    int m = idx / (VPITCH / 4);
    int k = (idx % (VPITCH / 4)) * 4;
    const float* xr = x + (size_t)m * NIN;
    float a[4];
#pragma unroll
    for (int j = 0; j < 4; j++) a[j] = (k + j < NIN) ? xr[k + j] : 0.f;

    size_t base = (size_t)m * KPAD + k;
#pragma unroll
    for (int v = 0; v < 4; v++) {
        union { __nv_bfloat16 b[4]; uint2 u; } ph, pl;
#pragma unroll
        for (int j = 0; j < 4; j++) {
            float t1 = fminf(fabsf(a[j]), 1.f);
            float val = (v == 0) ? a[j] : (v == 1) ? t1 : (v == 2) ? t1 * t1 : t1 * t1 * t1;
            __nv_bfloat16 h = __float2bfloat16_rn(val);
            ph.b[j] = h;
            pl.b[j] = __float2bfloat16_rn(val - __bfloat162float(h));
        }
        *(uint2*)&g_Ahi[base + (size_t)v * VPITCH] = ph.u;
        *(uint2*)&g_Alo[base + (size_t)v * VPITCH] = pl.u;
    }
}

__global__ void prep_B(const float* __restrict__ wkan, const float* __restrict__ d1,
                       const float* __restrict__ d2, const float* __restrict__ d3) {
    int idx = blockIdx.x * blockDim.x + threadIdx.x;      // over NHID * 176
    if (idx >= NHID * (VPITCH / 4)) return;
    int h = idx / (VPITCH / 4);
    int k = (idx % (VPITCH / 4)) * 4;
    size_t base = (size_t)h * KPAD + k;
#pragma unroll
    for (int v = 0; v < 4; v++) {
        const float* w = (v == 0) ? wkan : (v == 1) ? d1 : (v == 2) ? d2 : d3;
        union { __nv_bfloat16 b[4]; uint2 u; } ph, pl;
#pragma unroll
        for (int j = 0; j < 4; j++) {
            float val = (k + j < NIN) ? w[h * NIN + k + j] : 0.f;
            __nv_bfloat16 hh = __float2bfloat16_rn(val);
            ph.b[j] = hh;
            pl.b[j] = __float2bfloat16_rn(val - __bfloat162float(hh));
        }
        *(uint2*)&g_Bhi[base + (size_t)v * VPITCH] = ph.u;
        *(uint2*)&g_Blo[base + (size_t)v * VPITCH] = pl.u;
    }
}

__global__ void prep_wrec(const float* __restrict__ wrec) {
    int idx = blockIdx.x * blockDim.x + threadIdx.x;
    if (idx >= NHID * NHID) return;
    int j = idx / NHID;
    int h = idx - j * NHID;
    g_wrecT[idx] = wrec[h * NHID + j];
}

// ---------------- phase 1: mma.sync bf16x3 GEMM (unchanged from R14) --------
#define BM 128
#define BN 64
#define KC 32
#define NCHUNK (KPAD / KC)       // 88
#define O_AHI 0
#define O_ALO 8192
#define O_BHI 16384
#define O_BLO 20480
#define STAGE 24576
#define NSTG 2
#define SMEM_BYTES (NSTG * STAGE)   // 49152

__device__ __forceinline__ uint32_t smem_u32(const void* p) {
    uint32_t a;
    asm("{ .reg .u64 t; cvta.to.shared.u64 t, %1; cvt.u32.u64 %0, t; }" : "=r"(a) : "l"(p));
    return a;
}
__device__ __forceinline__ void cpa16(uint32_t s, const void* g) {
    asm volatile("cp.async.cg.shared.global [%0], [%1], 16;" :: "r"(s), "l"(g));
}

#define MMA_BF16(C, A, B) \
    asm volatile("mma.sync.aligned.m16n8k16.row.col.f32.bf16.bf16.f32 " \
                 "{%0,%1,%2,%3}, {%4,%5,%6,%7}, {%8,%9}, {%0,%1,%2,%3};" \
                 : "+f"((C)[0]), "+f"((C)[1]), "+f"((C)[2]), "+f"((C)[3]) \
                 : "r"((A)[0]), "r"((A)[1]), "r"((A)[2]), "r"((A)[3]), \
                   "r"((B)[0]), "r"((B)[1]))

#define LDMX4(r0, r1, r2, r3, addr) \
    asm volatile("ldmatrix.sync.aligned.m8n8.x4.shared.b16 {%0,%1,%2,%3}, [%4];" \
                 : "=r"(r0), "=r"(r1), "=r"(r2), "=r"(r3) : "r"(addr))

__global__ void __launch_bounds__(128, 4) gemm_mma() {
    extern __shared__ char smemc[];
    const uint32_t sb = smem_u32(smemc);
    const int tid = threadIdx.x;
    const int warp = tid >> 5;
    const int lane = tid & 31;
    const int wm = (warp >> 1) * 64;
    const int wn = (warp & 1) * 32;
    const int m0 = blockIdx.y * BM;
    const int n0 = blockIdx.x * BN;

    float acc[4][4][4];
#pragma unroll
    for (int i = 0; i < 4; i++)
#pragma unroll
        for (int j = 0; j < 4; j++)
#pragma unroll
            for (int q = 0; q < 4; q++) acc[i][j][q] = 0.f;

    const int ra = wm + ((lane >> 3) & 1) * 8 + (lane & 7);
    const int cba = lane >> 4;
    const int sa = (ra >> 1) & 3;
    const uint32_t a_row = (uint32_t)ra * 64;
    const uint32_t a_c0 = (uint32_t)((cba ^ sa) << 4);
    const uint32_t a_c1 = (uint32_t)(((cba + 2) ^ sa) << 4);
    const int rb = wn + ((lane >> 4) & 1) * 8 + (lane & 7);
    const int cbb = (lane >> 3) & 1;
    const int sbx = (rb >> 1) & 3;
    const uint32_t b_row = (uint32_t)rb * 64;
    const uint32_t b_c0 = (uint32_t)((cbb ^ sbx) << 4);
    const uint32_t b_c1 = (uint32_t)(((cbb + 2) ^ sbx) << 4);

    auto load_stage = [&](int s) {
        uint32_t b = sb + (uint32_t)(s & (NSTG - 1)) * STAGE;
        int kk0 = s * KC;
#pragma unroll
        for (int it = 0; it < 4; it++) {
            int i = it * 128 + tid;
            int r = i >> 2, c = i & 3;
            uint32_t so = (uint32_t)(r * 64 + ((c ^ ((r >> 1) & 3)) << 4));
            size_t ga = (size_t)(m0 + r) * KPAD + kk0 + c * 8;
            cpa16(b + O_AHI + so, &g_Ahi[ga]);
            cpa16(b + O_ALO + so, &g_Alo[ga]);
        }
#pragma unroll
        for (int it = 0; it < 2; it++) {
            int i = it * 128 + tid;
            int r = i >> 2, c = i & 3;
            uint32_t so = (uint32_t)(r * 64 + ((c ^ ((r >> 1) & 3)) << 4));
            size_t gb = (size_t)(n0 + r) * KPAD + kk0 + c * 8;
            cpa16(b + O_BHI + so, &g_Bhi[gb]);
            cpa16(b + O_BLO + so, &g_Blo[gb]);
        }
        asm volatile("cp.async.commit_group;" ::: "memory");
    };

    load_stage(0);

    for (int ch = 0; ch < NCHUNK; ch++) {
        if (ch + 1 < NCHUNK) {
            load_stage(ch + 1);
            asm volatile("cp.async.wait_group 1;" ::: "memory");
        } else {
            asm volatile("cp.async.wait_group 0;" ::: "memory");
        }
        __syncthreads();

        const uint32_t Sb = sb + (uint32_t)(ch & (NSTG - 1)) * STAGE;

#pragma unroll
        for (int ks = 0; ks < 2; ks++) {
            const uint32_t aco = ks ? a_c1 : a_c0;
            const uint32_t bco = ks ? b_c1 : b_c0;
            uint32_t af[4][4], bh[4][2], bl[4][2];

            LDMX4(bh[0][0], bh[0][1], bh[1][0], bh[1][1], Sb + O_BHI + b_row + bco);
            LDMX4(bh[2][0], bh[2][1], bh[3][0], bh[3][1], Sb + O_BHI + b_row + 1024 + bco);
            LDMX4(bl[0][0], bl[0][1], bl[1][0], bl[1][1], Sb + O_BLO + b_row + bco);
            LDMX4(bl[2][0], bl[2][1], bl[3][0], bl[3][1], Sb + O_BLO + b_row + 1024 + bco);

#pragma unroll
            for (int i = 0; i < 4; i++)
                LDMX4(af[i][0], af[i][1], af[i][2], af[i][3],
                      Sb + O_AHI + a_row + (uint32_t)i * 1024 + aco);
#pragma unroll
            for (int i = 0; i < 4; i++)
#pragma unroll
                for (int j = 0; j < 4; j++) MMA_BF16(acc[i][j], af[i], bh[j]);
#pragma unroll
            for (int i = 0; i < 4; i++)
#pragma unroll
                for (int j = 0; j < 4; j++) MMA_BF16(acc[i][j], af[i], bl[j]);
#pragma unroll
            for (int i = 0; i < 4; i++)
                LDMX4(af[i][0], af[i][1], af[i][2], af[i][3],
                      Sb + O_ALO + a_row + (uint32_t)i * 1024 + aco);
#pragma unroll
            for (int i = 0; i < 4; i++)
#pragma unroll
                for (int j = 0; j < 4; j++) MMA_BF16(acc[i][j], af[i], bh[j]);
        }
        __syncthreads();
    }

    {
        float* sC = (float*)smemc;             // [128][68]
#pragma unroll
        for (int i = 0; i < 4; i++) {
            int r = wm + i * 16 + (lane >> 2);
#pragma unroll
            for (int j = 0; j < 4; j++) {
                int c = wn + j * 8 + 2 * (lane & 3);
                sC[r * 68 + c]           = acc[i][j][0];
                sC[r * 68 + c + 1]       = acc[i][j][1];
                sC[(r + 8) * 68 + c]     = acc[i][j][2];
                sC[(r + 8) * 68 + c + 1] = acc[i][j][3];
            }
        }
        __syncthreads();
#pragma unroll
        for (int it = 0; it < 16; it++) {
            int i = tid + it * 128;
            int r = i >> 4, c4 = (i & 15) * 4;
            float4 v = *(float4*)&sC[r * 68 + c4];
            *(float4*)&g_iin[(size_t)(m0 + r) * NHID + n0 + c4] = v;
        }
    }
}

// ---------------- phase 2: persistent per-batch recurrence (optimized) ------
// 2 barriers/step, double-buffered spike list, 8-way MLP gather, i_in prefetch.
__global__ void __launch_bounds__(512) snn_seq(const float* __restrict__ wout,
                                               float* __restrict__ out) {
    __shared__ float s_wout[NOUT * NHID];       // 40 KB
    __shared__ unsigned s_mask[16];
    __shared__ int   s_list[2][NHID];
    __shared__ int   s_cnt;
    __shared__ float s_iout[NOUT];

    const int b = blockIdx.x;
    const int h = threadIdx.x;
    const int warp = h >> 5;
    const int lane = h & 31;

    for (int i = h; i < NOUT * NHID; i += 512) s_wout[i] = wout[i];
    if (h == 0) s_cnt = 0;

    float v1 = 0.f, a1 = 0.f, s_prev = 0.f;
    float v_out = 0.f, acc_out = 0.f;

    const float* iin_b = &g_iin[(size_t)b * TSTEPS * NHID];
    float iin_cur = __ldg(&iin_b[h]);          // t = 0

    __syncthreads();

    for (int t = 0; t < TSTEPS; t++) {
        const int wb = t & 1;                  // write buffer this step
        // ---- phase 1: gather recurrent input from prev-step list ----
        const int cnt = s_cnt;
        const int* lst = s_list[wb ^ 1];
        float r0 = 0.f, r1 = 0.f, r2 = 0.f, r3 = 0.f;
        float r4 = 0.f, r5 = 0.f, r6 = 0.f, r7 = 0.f;
        int k = 0;
        for (; k + 8 <= cnt; k += 8) {
            int j0 = lst[k],     j1 = lst[k + 1], j2 = lst[k + 2], j3 = lst[k + 3];
            int j4 = lst[k + 4], j5 = lst[k + 5], j6 = lst[k + 6], j7 = lst[k + 7];
            r0 += __ldg(&g_wrecT[(size_t)j0 * NHID + h]);
            r1 += __ldg(&g_wrecT[(size_t)j1 * NHID + h]);
            r2 += __ldg(&g_wrecT[(size_t)j2 * NHID + h]);
            r3 += __ldg(&g_wrecT[(size_t)j3 * NHID + h]);
            r4 += __ldg(&g_wrecT[(size_t)j4 * NHID + h]);
            r5 += __ldg(&g_wrecT[(size_t)j5 * NHID + h]);
            r6 += __ldg(&g_wrecT[(size_t)j6 * NHID + h]);
            r7 += __ldg(&g_wrecT[(size_t)j7 * NHID + h]);
        }
        for (; k < cnt; k++) r0 += __ldg(&g_wrecT[(size_t)lst[k] * NHID + h]);
        const float rec = ((r0 + r1) + (r2 + r3)) + ((r4 + r5) + (r6 + r7));

        // prefetch next step's feedforward input (hides DRAM latency)
        float iin_next = 0.f;
        if (t + 1 < TSTEPS) iin_next = __ldg(&iin_b[(size_t)(t + 1) * NHID + h]);

        // ---- LIF update ----
        const float i1 = iin_cur + rec;
        v1 = 0.95f * v1 + 0.05f * i1 - 1.0f * s_prev;
        a1 = 0.85f * a1 + 0.15f * s_prev;
        const float thr = 1.0f + 0.05f * a1;
        const float s_new = (v1 > thr) ? 1.f : 0.f;

        const unsigned mask = __ballot_sync(0xffffffffu, s_new > 0.f);
        if (lane == 0) s_mask[warp] = mask;

        __syncthreads();   // masks visible; everyone done reading old list

        // ---- build new spike list (deterministic order) ----
        int base = 0, tot = 0;
#pragma unroll
        for (int w = 0; w < 16; w++) {
            int c = __popc(s_mask[w]);
            base += (w < warp) ? c : 0;
            tot += c;
        }
        if (s_new > 0.f) {
            int pos = base + __popc(mask & ((1u << lane) - 1u));
            s_list[wb][pos] = h;
        }
        if (h == 0) s_cnt = tot;

        // ---- readout from ballot masks (predicated loads) ----
        for (int o = warp; o < NOUT; o += 16) {
            float p = 0.f;
            const float* wrow = &s_wout[o * NHID];
#pragma unroll
            for (int wi = 0; wi < 16; wi++) {
                if ((s_mask[wi] >> lane) & 1u) p += wrow[wi * 32 + lane];
            }
#pragma unroll
            for (int off = 16; off > 0; off >>= 1)
                p += __shfl_down_sync(0xffffffffu, p, off);
            if (lane == 0) s_iout[o] = p;
        }

        __syncthreads();   // new list + s_cnt + s_iout visible

        if (h < NOUT) {
            v_out = 0.9f * v_out + s_iout[h];
            const float s_o = (v_out > 1.0f) ? 1.f : 0.f;
            v_out = v_out - 1.0f * s_o;
            acc_out += v_out;
        }

        s_prev = s_new;
        iin_cur = iin_next;
    }

    if (h < NOUT) out[b * NOUT + h] = acc_out * (1.0f / (float)TSTEPS);
}

// ---------------- launch -----------------------------------------------------
extern "C" void kernel_launch(void* const* d_in, const int* in_sizes, int n_in,
                              void* d_out, int out_size) {
    const float* x    = (const float*)d_in[0];
    const float* wkan = (const float*)d_in[1];
    const float* d1   = (const float*)d_in[2];
    const float* d2   = (const float*)d_in[3];
    const float* d3   = (const float*)d_in[4];
    const float* wrec = (const float*)d_in[5];
    const float* wout = (const float*)d_in[6];
    float* out = (float*)d_out;

    cudaFuncSetAttribute(gemm_mma, cudaFuncAttributeMaxDynamicSharedMemorySize, SMEM_BYTES);

    prep_A<<<(MROWS * (VPITCH / 4) + 255) / 256, 256>>>(x);
    prep_B<<<(NHID * (VPITCH / 4) + 255) / 256, 256>>>(wkan, d1, d2, d3);
    prep_wrec<<<(NHID * NHID + 255) / 256, 256>>>(wrec);

    dim3 grid(NHID / BN, MROWS / BM);   // (8, 500)
    gemm_mma<<<grid, 128, SMEM_BYTES>>>();

    snn_seq<<<BATCH, 512>>>(wout, out);
}

// round 16
// speedup vs baseline: 1.3364x; 1.0703x over previous
#include <cuda_runtime.h>
#include <cuda_bf16.h>
#include <cuda_fp16.h>
#include <cstdint>

#define BATCH 256
#define TSTEPS 250
#define NIN 700
#define NHID 512
#define NOUT 20
#define VPITCH 704            // per-variant padded K
#define KPAD (4*VPITCH)       // 2816
#define MROWS (BATCH*TSTEPS)  // 64000

// ---------------- device scratch (no allocations allowed) -------------------
__device__ float g_iin[(size_t)MROWS * NHID];
__device__ uint2 g_wrecP[(size_t)NHID * 128];     // [j][t]: halves {t, t+128, t+256, t+384}
__device__ __nv_bfloat16 g_Ahi[(size_t)MROWS * KPAD];
__device__ __nv_bfloat16 g_Alo[(size_t)MROWS * KPAD];
__device__ __nv_bfloat16 g_Bhi[(size_t)NHID * KPAD];
__device__ __nv_bfloat16 g_Blo[(size_t)NHID * KPAD];

// ---------------- prep kernels ----------------------------------------------
__global__ void prep_A(const float* __restrict__ x) {
    int idx = blockIdx.x * blockDim.x + threadIdx.x;      // over MROWS * 176
    if (idx >= MROWS * (VPITCH / 4)) return;
    int m = idx / (VPITCH / 4);
    int k = (idx % (VPITCH / 4)) * 4;
    const float* xr = x + (size_t)m * NIN;
    float a[4];
#pragma unroll
    for (int j = 0; j < 4; j++) a[j] = (k + j < NIN) ? xr[k + j] : 0.f;

    size_t base = (size_t)m * KPAD + k;
#pragma unroll
    for (int v = 0; v < 4; v++) {
        union { __nv_bfloat16 b[4]; uint2 u; } ph, pl;
#pragma unroll
        for (int j = 0; j < 4; j++) {
            float t1 = fminf(fabsf(a[j]), 1.f);
            float val = (v == 0) ? a[j] : (v == 1) ? t1 : (v == 2) ? t1 * t1 : t1 * t1 * t1;
            __nv_bfloat16 h = __float2bfloat16_rn(val);
            ph.b[j] = h;
            pl.b[j] = __float2bfloat16_rn(val - __bfloat162float(h));
        }
        *(uint2*)&g_Ahi[base + (size_t)v * VPITCH] = ph.u;
        *(uint2*)&g_Alo[base + (size_t)v * VPITCH] = pl.u;
    }
}

__global__ void prep_B(const float* __restrict__ wkan, const float* __restrict__ d1,
                       const float* __restrict__ d2, const float* __restrict__ d3) {
    int idx = blockIdx.x * blockDim.x + threadIdx.x;      // over NHID * 176
    if (idx >= NHID * (VPITCH / 4)) return;
    int h = idx / (VPITCH / 4);
    int k = (idx % (VPITCH / 4)) * 4;
    size_t base = (size_t)h * KPAD + k;
#pragma unroll
    for (int v = 0; v < 4; v++) {
        const float* w = (v == 0) ? wkan : (v == 1) ? d1 : (v == 2) ? d2 : d3;
        union { __nv_bfloat16 b[4]; uint2 u; } ph, pl;
#pragma unroll
        for (int j = 0; j < 4; j++) {
            float val = (k + j < NIN) ? w[h * NIN + k + j] : 0.f;
            __nv_bfloat16 hh = __float2bfloat16_rn(val);
            ph.b[j] = hh;
            pl.b[j] = __float2bfloat16_rn(val - __bfloat162float(hh));
        }
        *(uint2*)&g_Bhi[base + (size_t)v * VPITCH] = ph.u;
        *(uint2*)&g_Blo[base + (size_t)v * VPITCH] = pl.u;
    }
}

// pack w_rec^T into fp16 4-wide groups: P[j][t] = {w[t][j], w[t+128][j], w[t+256][j], w[t+384][j]}
__global__ void prep_wrec(const float* __restrict__ wrec) {
    int idx = blockIdx.x * blockDim.x + threadIdx.x;      // over NHID*128
    if (idx >= NHID * 128) return;
    int j = idx >> 7;
    int t = idx & 127;
    __half2 lo = __halves2half2(__float2half_rn(wrec[(size_t)t * NHID + j]),
                                __float2half_rn(wrec[(size_t)(t + 128) * NHID + j]));
    __half2 hi = __halves2half2(__float2half_rn(wrec[(size_t)(t + 256) * NHID + j]),
                                __float2half_rn(wrec[(size_t)(t + 384) * NHID + j]));
    uint2 u;
    u.x = *(uint32_t*)&lo;
    u.y = *(uint32_t*)&hi;
    g_wrecP[(size_t)j * 128 + t] = u;
}

// ---------------- phase 1: mma.sync bf16x3 GEMM (unchanged from R14) --------
#define BM 128
#define BN 64
#define KC 32
#define NCHUNK (KPAD / KC)       // 88
#define O_AHI 0
#define O_ALO 8192
#define O_BHI 16384
#define O_BLO 20480
#define STAGE 24576
#define NSTG 2
#define SMEM_BYTES (NSTG * STAGE)   // 49152

__device__ __forceinline__ uint32_t smem_u32(const void* p) {
    uint32_t a;
    asm("{ .reg .u64 t; cvta.to.shared.u64 t, %1; cvt.u32.u64 %0, t; }" : "=r"(a) : "l"(p));
    return a;
}
__device__ __forceinline__ void cpa16(uint32_t s, const void* g) {
    asm volatile("cp.async.cg.shared.global [%0], [%1], 16;" :: "r"(s), "l"(g));
}

#define MMA_BF16(C, A, B) \
    asm volatile("mma.sync.aligned.m16n8k16.row.col.f32.bf16.bf16.f32 " \
                 "{%0,%1,%2,%3}, {%4,%5,%6,%7}, {%8,%9}, {%0,%1,%2,%3};" \
                 : "+f"((C)[0]), "+f"((C)[1]), "+f"((C)[2]), "+f"((C)[3]) \
                 : "r"((A)[0]), "r"((A)[1]), "r"((A)[2]), "r"((A)[3]), \
                   "r"((B)[0]), "r"((B)[1]))

#define LDMX4(r0, r1, r2, r3, addr) \
    asm volatile("ldmatrix.sync.aligned.m8n8.x4.shared.b16 {%0,%1,%2,%3}, [%4];" \
                 : "=r"(r0), "=r"(r1), "=r"(r2), "=r"(r3) : "r"(addr))

__global__ void __launch_bounds__(128, 4) gemm_mma() {
    extern __shared__ char smemc[];
    const uint32_t sb = smem_u32(smemc);
    const int tid = threadIdx.x;
    const int warp = tid >> 5;
    const int lane = tid & 31;
    const int wm = (warp >> 1) * 64;
    const int wn = (warp & 1) * 32;
    const int m0 = blockIdx.y * BM;
    const int n0 = blockIdx.x * BN;

    float acc[4][4][4];
#pragma unroll
    for (int i = 0; i < 4; i++)
#pragma unroll
        for (int j = 0; j < 4; j++)
#pragma unroll
            for (int q = 0; q < 4; q++) acc[i][j][q] = 0.f;

    const int ra = wm + ((lane >> 3) & 1) * 8 + (lane & 7);
    const int cba = lane >> 4;
    const int sa = (ra >> 1) & 3;
    const uint32_t a_row = (uint32_t)ra * 64;
    const uint32_t a_c0 = (uint32_t)((cba ^ sa) << 4);
    const uint32_t a_c1 = (uint32_t)(((cba + 2) ^ sa) << 4);
    const int rb = wn + ((lane >> 4) & 1) * 8 + (lane & 7);
    const int cbb = (lane >> 3) & 1;
    const int sbx = (rb >> 1) & 3;
    const uint32_t b_row = (uint32_t)rb * 64;
    const uint32_t b_c0 = (uint32_t)((cbb ^ sbx) << 4);
    const uint32_t b_c1 = (uint32_t)(((cbb + 2) ^ sbx) << 4);

    auto load_stage = [&](int s) {
        uint32_t b = sb + (uint32_t)(s & (NSTG - 1)) * STAGE;
        int kk0 = s * KC;
#pragma unroll
        for (int it = 0; it < 4; it++) {
            int i = it * 128 + tid;
            int r = i >> 2, c = i & 3;
            uint32_t so = (uint32_t)(r * 64 + ((c ^ ((r >> 1) & 3)) << 4));
            size_t ga = (size_t)(m0 + r) * KPAD + kk0 + c * 8;
            cpa16(b + O_AHI + so, &g_Ahi[ga]);
            cpa16(b + O_ALO + so, &g_Alo[ga]);
        }
#pragma unroll
        for (int it = 0; it < 2; it++) {
            int i = it * 128 + tid;
            int r = i >> 2, c = i & 3;
            uint32_t so = (uint32_t)(r * 64 + ((c ^ ((r >> 1) & 3)) << 4));
            size_t gb = (size_t)(n0 + r) * KPAD + kk0 + c * 8;
            cpa16(b + O_BHI + so, &g_Bhi[gb]);
            cpa16(b + O_BLO + so, &g_Blo[gb]);
        }
        asm volatile("cp.async.commit_group;" ::: "memory");
    };

    load_stage(0);

    for (int ch = 0; ch < NCHUNK; ch++) {
        if (ch + 1 < NCHUNK) {
            load_stage(ch + 1);
            asm volatile("cp.async.wait_group 1;" ::: "memory");
        } else {
            asm volatile("cp.async.wait_group 0;" ::: "memory");
        }
        __syncthreads();

        const uint32_t Sb = sb + (uint32_t)(ch & (NSTG - 1)) * STAGE;

#pragma unroll
        for (int ks = 0; ks < 2; ks++) {
            const uint32_t aco = ks ? a_c1 : a_c0;
            const uint32_t bco = ks ? b_c1 : b_c0;
            uint32_t af[4][4], bh[4][2], bl[4][2];

            LDMX4(bh[0][0], bh[0][1], bh[1][0], bh[1][1], Sb + O_BHI + b_row + bco);
            LDMX4(bh[2][0], bh[2][1], bh[3][0], bh[3][1], Sb + O_BHI + b_row + 1024 + bco);
            LDMX4(bl[0][0], bl[0][1], bl[1][0], bl[1][1], Sb + O_BLO + b_row + bco);
            LDMX4(bl[2][0], bl[2][1], bl[3][0], bl[3][1], Sb + O_BLO + b_row + 1024 + bco);

#pragma unroll
            for (int i = 0; i < 4; i++)
                LDMX4(af[i][0], af[i][1], af[i][2], af[i][3],
                      Sb + O_AHI + a_row + (uint32_t)i * 1024 + aco);
#pragma unroll
            for (int i = 0; i < 4; i++)
#pragma unroll
                for (int j = 0; j < 4; j++) MMA_BF16(acc[i][j], af[i], bh[j]);
#pragma unroll
            for (int i = 0; i < 4; i++)
#pragma unroll
                for (int j = 0; j < 4; j++) MMA_BF16(acc[i][j], af[i], bl[j]);
#pragma unroll
            for (int i = 0; i < 4; i++)
                LDMX4(af[i][0], af[i][1], af[i][2], af[i][3],
                      Sb + O_ALO + a_row + (uint32_t)i * 1024 + aco);
#pragma unroll
            for (int i = 0; i < 4; i++)
#pragma unroll
                for (int j = 0; j < 4; j++) MMA_BF16(acc[i][j], af[i], bh[j]);
        }
        __syncthreads();
    }

    {
        float* sC = (float*)smemc;             // [128][68]
#pragma unroll
        for (int i = 0; i < 4; i++) {
            int r = wm + i * 16 + (lane >> 2);
#pragma unroll
            for (int j = 0; j < 4; j++) {
                int c = wn + j * 8 + 2 * (lane & 3);
                sC[r * 68 + c]           = acc[i][j][0];
                sC[r * 68 + c + 1]       = acc[i][j][1];
                sC[(r + 8) * 68 + c]     = acc[i][j][2];
                sC[(r + 8) * 68 + c + 1] = acc[i][j][3];
            }
        }
        __syncthreads();
#pragma unroll
        for (int it = 0; it < 16; it++) {
            int i = tid + it * 128;
            int r = i >> 4, c4 = (i & 15) * 4;
            float4 v = *(float4*)&sC[r * 68 + c4];
            *(float4*)&g_iin[(size_t)(m0 + r) * NHID + n0 + c4] = v;
        }
    }
}

// ---------------- phase 2: recurrence, 128 threads x 4 neurons/thread -------
__global__ void __launch_bounds__(128) snn_seq(const float* __restrict__ wout,
                                               float* __restrict__ out) {
    __shared__ float s_wout[NOUT * NHID];       // 40 KB, [o][h]
    __shared__ unsigned s_mask[16];             // idx = g*4 + warp
    __shared__ int   s_list[2][NHID];
    __shared__ int   s_cnt;
    __shared__ float s_iout[NOUT];

    const int b = blockIdx.x;
    const int t = threadIdx.x;                  // 0..127
    const int w = t >> 5;
    const int lane = t & 31;

    for (int i = t; i < NOUT * NHID; i += 128) s_wout[i] = wout[i];
    if (t == 0) s_cnt = 0;

    float v1[4] = {0.f, 0.f, 0.f, 0.f};
    float a1[4] = {0.f, 0.f, 0.f, 0.f};
    float sp[4] = {0.f, 0.f, 0.f, 0.f};
    float v_out = 0.f, acc_out = 0.f;

    const float* iin_b = &g_iin[(size_t)b * TSTEPS * NHID];
    float cur[4];
#pragma unroll
    for (int g = 0; g < 4; g++) cur[g] = __ldg(&iin_b[g * 128 + t]);

    __syncthreads();

    const uint2* wp = g_wrecP;

    for (int ts = 0; ts < TSTEPS; ts++) {
        const int wb = ts & 1;
        const int cnt = s_cnt;
        const int* lst = s_list[wb ^ 1];

        float r[4] = {0.f, 0.f, 0.f, 0.f};
        int k = 0;
        for (; k + 8 <= cnt; k += 8) {
            uint2 u[8];
#pragma unroll
            for (int q = 0; q < 8; q++)
                u[q] = __ldg(&wp[(size_t)lst[k + q] * 128 + t]);
#pragma unroll
            for (int q = 0; q < 8; q++) {
                float2 f0 = __half22float2(*(__half2*)&u[q].x);
                float2 f1 = __half22float2(*(__half2*)&u[q].y);
                r[0] += f0.x; r[1] += f0.y; r[2] += f1.x; r[3] += f1.y;
            }
        }
        for (; k < cnt; k++) {
            uint2 u = __ldg(&wp[(size_t)lst[k] * 128 + t]);
            float2 f0 = __half22float2(*(__half2*)&u.x);
            float2 f1 = __half22float2(*(__half2*)&u.y);
            r[0] += f0.x; r[1] += f0.y; r[2] += f1.x; r[3] += f1.y;
        }

        // prefetch next feedforward input
        float nxt[4] = {0.f, 0.f, 0.f, 0.f};
        if (ts + 1 < TSTEPS) {
#pragma unroll
            for (int g = 0; g < 4; g++)
                nxt[g] = __ldg(&iin_b[(size_t)(ts + 1) * NHID + g * 128 + t]);
        }

        // ---- LIF update (4 neurons) + ballots ----
        float sn[4];
        unsigned m[4];
#pragma unroll
        for (int g = 0; g < 4; g++) {
            const float i1 = cur[g] + r[g];
            v1[g] = 0.95f * v1[g] + 0.05f * i1 - sp[g];
            a1[g] = 0.85f * a1[g] + 0.15f * sp[g];
            sn[g] = (v1[g] > 1.0f + 0.05f * a1[g]) ? 1.f : 0.f;
            m[g] = __ballot_sync(0xffffffffu, sn[g] > 0.f);
        }
        if (lane == 0) {
#pragma unroll
            for (int g = 0; g < 4; g++) s_mask[g * 4 + w] = m[g];
        }

        __syncthreads();   // masks visible; everyone done reading old list

        // ---- build new spike list (deterministic neuron order g*128+w*32+lane) ----
        int pre[4];
        int run = 0;
#pragma unroll
        for (int idx = 0; idx < 16; idx++) {
            int pc = __popc(s_mask[idx]);
#pragma unroll
            for (int g = 0; g < 4; g++)
                if (idx == g * 4 + w) pre[g] = run;
            run += pc;
        }
#pragma unroll
        for (int g = 0; g < 4; g++) {
            if (sn[g] > 0.f) {
                int pos = pre[g] + __popc(m[g] & ((1u << lane) - 1u));
                s_list[wb][pos] = g * 128 + w * 32 + lane;
            }
        }
        if (t == 0) s_cnt = run;

        // ---- readout via mask-predicated loads ----
        for (int o = w; o < NOUT; o += 4) {
            float p = 0.f;
            const float* wrow = &s_wout[o * NHID];
#pragma unroll
            for (int idx = 0; idx < 16; idx++) {
                unsigned mm = s_mask[idx];
                if ((mm >> lane) & 1u)
                    p += wrow[(idx >> 2) * 128 + (idx & 3) * 32 + lane];
            }
#pragma unroll
            for (int off = 16; off > 0; off >>= 1)
                p += __shfl_down_sync(0xffffffffu, p, off);
            if (lane == 0) s_iout[o] = p;
        }

        __syncthreads();   // new list + s_cnt + s_iout visible

        if (t < NOUT) {
            v_out = 0.9f * v_out + s_iout[t];
            const float s_o = (v_out > 1.0f) ? 1.f : 0.f;
            v_out = v_out - 1.0f * s_o;
            acc_out += v_out;
        }

#pragma unroll
        for (int g = 0; g < 4; g++) { sp[g] = sn[g]; cur[g] = nxt[g]; }
    }

    if (t < NOUT) out[b * NOUT + t] = acc_out * (1.0f / (float)TSTEPS);
}

// ---------------- launch -----------------------------------------------------
extern "C" void kernel_launch(void* const* d_in, const int* in_sizes, int n_in,
                              void* d_out, int out_size) {
    const float* x    = (const float*)d_in[0];
    const float* wkan = (const float*)d_in[1];
    const float* d1   = (const float*)d_in[2];
    const float* d2   = (const float*)d_in[3];
    const float* d3   = (const float*)d_in[4];
    const float* wrec = (const float*)d_in[5];
    const float* wout = (const float*)d_in[6];
    float* out = (float*)d_out;

    cudaFuncSetAttribute(gemm_mma, cudaFuncAttributeMaxDynamicSharedMemorySize, SMEM_BYTES);

    prep_A<<<(MROWS * (VPITCH / 4) + 255) / 256, 256>>>(x);
    prep_B<<<(NHID * (VPITCH / 4) + 255) / 256, 256>>>(wkan, d1, d2, d3);
    prep_wrec<<<(NHID * 128 + 255) / 256, 256>>>(wrec);

    dim3 grid(NHID / BN, MROWS / BM);   // (8, 500)
    gemm_mma<<<grid, 128, SMEM_BYTES>>>();

    snn_seq<<<BATCH, 128>>>(wout, out);
}

// round 17
// speedup vs baseline: 1.8248x; 1.3655x over previous
#include <cuda_runtime.h>
#include <cuda_fp16.h>
#include <cstdint>

#define BATCH 256
#define TSTEPS 250
#define NIN 700
#define NHID 512
#define NOUT 20
#define VPITCH 704            // per-variant padded K
#define KPAD (4*VPITCH)       // 2816
#define MROWS (BATCH*TSTEPS)  // 64000

// ---------------- device scratch (no allocations allowed) -------------------
__device__ float g_iin[(size_t)MROWS * NHID];
__device__ uint2 g_wrecP[(size_t)NHID * 128];     // [j][t]: halves {t,t+128,t+256,t+384}
__device__ __half g_A[(size_t)MROWS * KPAD];      // fp16(transformed x)
__device__ __half g_Bh[(size_t)NHID * KPAD];      // fp16 hi of concat weights
__device__ __half g_Bl[(size_t)NHID * KPAD];      // fp16 lo

// ---------------- prep kernels ----------------------------------------------
__global__ void prep_A(const float* __restrict__ x) {
    int idx = blockIdx.x * blockDim.x + threadIdx.x;      // over MROWS * 176
    if (idx >= MROWS * (VPITCH / 4)) return;
    int m = idx / (VPITCH / 4);
    int k = (idx % (VPITCH / 4)) * 4;
    const float* xr = x + (size_t)m * NIN;
    float a[4];
#pragma unroll
    for (int j = 0; j < 4; j++) a[j] = (k + j < NIN) ? xr[k + j] : 0.f;

    size_t base = (size_t)m * KPAD + k;
#pragma unroll
    for (int v = 0; v < 4; v++) {
        union { __half b[4]; uint2 u; } p;
#pragma unroll
        for (int j = 0; j < 4; j++) {
            float t1 = fminf(fabsf(a[j]), 1.f);
            float val = (v == 0) ? a[j] : (v == 1) ? t1 : (v == 2) ? t1 * t1 : t1 * t1 * t1;
            p.b[j] = __float2half_rn(val);
        }
        *(uint2*)&g_A[base + (size_t)v * VPITCH] = p.u;
    }
}

__global__ void prep_B(const float* __restrict__ wkan, const float* __restrict__ d1,
                       const float* __restrict__ d2, const float* __restrict__ d3) {
    int idx = blockIdx.x * blockDim.x + threadIdx.x;      // over NHID * 176
    if (idx >= NHID * (VPITCH / 4)) return;
    int h = idx / (VPITCH / 4);
    int k = (idx % (VPITCH / 4)) * 4;
    size_t base = (size_t)h * KPAD + k;
#pragma unroll
    for (int v = 0; v < 4; v++) {
        const float* w = (v == 0) ? wkan : (v == 1) ? d1 : (v == 2) ? d2 : d3;
        union { __half b[4]; uint2 u; } ph, pl;
#pragma unroll
        for (int j = 0; j < 4; j++) {
            float val = (k + j < NIN) ? w[h * NIN + k + j] : 0.f;
            __half hh = __float2half_rn(val);
            ph.b[j] = hh;
            pl.b[j] = __float2half_rn(val - __half2float(hh));
        }
        *(uint2*)&g_Bh[base + (size_t)v * VPITCH] = ph.u;
        *(uint2*)&g_Bl[base + (size_t)v * VPITCH] = pl.u;
    }
}

// pack w_rec^T into fp16 4-wide groups
__global__ void prep_wrec(const float* __restrict__ wrec) {
    int idx = blockIdx.x * blockDim.x + threadIdx.x;      // over NHID*128
    if (idx >= NHID * 128) return;
    int j = idx >> 7;
    int t = idx & 127;
    __half2 lo = __halves2half2(__float2half_rn(wrec[(size_t)t * NHID + j]),
                                __float2half_rn(wrec[(size_t)(t + 128) * NHID + j]));
    __half2 hi = __halves2half2(__float2half_rn(wrec[(size_t)(t + 256) * NHID + j]),
                                __float2half_rn(wrec[(size_t)(t + 384) * NHID + j]));
    uint2 u;
    u.x = *(uint32_t*)&lo;
    u.y = *(uint32_t*)&hi;
    g_wrecP[(size_t)j * 128 + t] = u;
}

// ---------------- phase 1: mma.sync fp16x2 GEMM -----------------------------
// C = A Bh^T + A Bl^T,  128x64 tiles, KC=32, swizzled pitch-64, 2 stages.
#define BM 128
#define BN 64
#define KC 32
#define NCHUNK (KPAD / KC)       // 88
#define O_A  0
#define O_BH 8192
#define O_BL 12288
#define STAGE 16384
#define NSTG 2
#define SMEM_BYTES (NSTG * STAGE)   // 32768

__device__ __forceinline__ uint32_t smem_u32(const void* p) {
    uint32_t a;
    asm("{ .reg .u64 t; cvta.to.shared.u64 t, %1; cvt.u32.u64 %0, t; }" : "=r"(a) : "l"(p));
    return a;
}
__device__ __forceinline__ void cpa16(uint32_t s, const void* g) {
    asm volatile("cp.async.cg.shared.global [%0], [%1], 16;" :: "r"(s), "l"(g));
}

#define MMA_F16(C, A, B) \
    asm volatile("mma.sync.aligned.m16n8k16.row.col.f32.f16.f16.f32 " \
                 "{%0,%1,%2,%3}, {%4,%5,%6,%7}, {%8,%9}, {%0,%1,%2,%3};" \
                 : "+f"((C)[0]), "+f"((C)[1]), "+f"((C)[2]), "+f"((C)[3]) \
                 : "r"((A)[0]), "r"((A)[1]), "r"((A)[2]), "r"((A)[3]), \
                   "r"((B)[0]), "r"((B)[1]))

#define LDMX4(r0, r1, r2, r3, addr) \
    asm volatile("ldmatrix.sync.aligned.m8n8.x4.shared.b16 {%0,%1,%2,%3}, [%4];" \
                 : "=r"(r0), "=r"(r1), "=r"(r2), "=r"(r3) : "r"(addr))

__global__ void __launch_bounds__(128, 4) gemm_mma() {
    extern __shared__ char smemc[];
    const uint32_t sb = smem_u32(smemc);
    const int tid = threadIdx.x;
    const int warp = tid >> 5;
    const int lane = tid & 31;
    const int wm = (warp >> 1) * 64;
    const int wn = (warp & 1) * 32;
    const int m0 = blockIdx.y * BM;
    const int n0 = blockIdx.x * BN;

    float acc[4][4][4];
#pragma unroll
    for (int i = 0; i < 4; i++)
#pragma unroll
        for (int j = 0; j < 4; j++)
#pragma unroll
            for (int q = 0; q < 4; q++) acc[i][j][q] = 0.f;

    // ldmatrix per-lane addressing (XOR swizzle, pitch 64B)
    const int ra = wm + ((lane >> 3) & 1) * 8 + (lane & 7);
    const int cba = lane >> 4;
    const int sa = (ra >> 1) & 3;
    const uint32_t a_row = (uint32_t)ra * 64;
    const uint32_t a_c0 = (uint32_t)((cba ^ sa) << 4);
    const uint32_t a_c1 = (uint32_t)(((cba + 2) ^ sa) << 4);
    const int rb = wn + ((lane >> 4) & 1) * 8 + (lane & 7);
    const int cbb = (lane >> 3) & 1;
    const int sbx = (rb >> 1) & 3;
    const uint32_t b_row = (uint32_t)rb * 64;
    const uint32_t b_c0 = (uint32_t)((cbb ^ sbx) << 4);
    const uint32_t b_c1 = (uint32_t)(((cbb + 2) ^ sbx) << 4);

    auto load_stage = [&](int s) {
        uint32_t b = sb + (uint32_t)(s & (NSTG - 1)) * STAGE;
        int kk0 = s * KC;
        // A: 128 rows x 4 chunks = 512 chunks, 4 iters
#pragma unroll
        for (int it = 0; it < 4; it++) {
            int i = it * 128 + tid;
            int r = i >> 2, c = i & 3;
            uint32_t so = (uint32_t)(r * 64 + ((c ^ ((r >> 1) & 3)) << 4));
            size_t ga = (size_t)(m0 + r) * KPAD + kk0 + c * 8;
            cpa16(b + O_A + so, &g_A[ga]);
        }
        // Bh/Bl: 64 rows x 4 chunks = 256 chunks, 2 iters each
#pragma unroll
        for (int it = 0; it < 2; it++) {
            int i = it * 128 + tid;
            int r = i >> 2, c = i & 3;
            uint32_t so = (uint32_t)(r * 64 + ((c ^ ((r >> 1) & 3)) << 4));
            size_t gb = (size_t)(n0 + r) * KPAD + kk0 + c * 8;
            cpa16(b + O_BH + so, &g_Bh[gb]);
            cpa16(b + O_BL + so, &g_Bl[gb]);
        }
        asm volatile("cp.async.commit_group;" ::: "memory");
    };

    load_stage(0);

    for (int ch = 0; ch < NCHUNK; ch++) {
        if (ch + 1 < NCHUNK) {
            load_stage(ch + 1);
            asm volatile("cp.async.wait_group 1;" ::: "memory");
        } else {
            asm volatile("cp.async.wait_group 0;" ::: "memory");
        }
        __syncthreads();

        const uint32_t Sb = sb + (uint32_t)(ch & (NSTG - 1)) * STAGE;

#pragma unroll
        for (int ks = 0; ks < 2; ks++) {
            const uint32_t aco = ks ? a_c1 : a_c0;
            const uint32_t bco = ks ? b_c1 : b_c0;
            uint32_t af[4][4], bh[4][2], bl[4][2];

            LDMX4(bh[0][0], bh[0][1], bh[1][0], bh[1][1], Sb + O_BH + b_row + bco);
            LDMX4(bh[2][0], bh[2][1], bh[3][0], bh[3][1], Sb + O_BH + b_row + 1024 + bco);
            LDMX4(bl[0][0], bl[0][1], bl[1][0], bl[1][1], Sb + O_BL + b_row + bco);
            LDMX4(bl[2][0], bl[2][1], bl[3][0], bl[3][1], Sb + O_BL + b_row + 1024 + bco);

#pragma unroll
            for (int i = 0; i < 4; i++)
                LDMX4(af[i][0], af[i][1], af[i][2], af[i][3],
                      Sb + O_A + a_row + (uint32_t)i * 1024 + aco);
            // pass 1: A x Bh
#pragma unroll
            for (int i = 0; i < 4; i++)
#pragma unroll
                for (int j = 0; j < 4; j++) MMA_F16(acc[i][j], af[i], bh[j]);
            // pass 2: A x Bl
#pragma unroll
            for (int i = 0; i < 4; i++)
#pragma unroll
                for (int j = 0; j < 4; j++) MMA_F16(acc[i][j], af[i], bl[j]);
        }
        __syncthreads();
    }

    // ---- epilogue ----
    {
        float* sC = (float*)smemc;             // [128][68] uses 34.8KB > 32KB? no: epilogue reuses full smem alloc
#pragma unroll
        for (int i = 0; i < 4; i++) {
            int r = wm + i * 16 + (lane >> 2);
#pragma unroll
            for (int j = 0; j < 4; j++) {
                int c = wn + j * 8 + 2 * (lane & 3);
                sC[r * 68 + c]           = acc[i][j][0];
                sC[r * 68 + c + 1]       = acc[i][j][1];
                sC[(r + 8) * 68 + c]     = acc[i][j][2];
                sC[(r + 8) * 68 + c + 1] = acc[i][j][3];
            }
        }
        __syncthreads();
#pragma unroll
        for (int it = 0; it < 16; it++) {
            int i = tid + it * 128;
            int r = i >> 4, c4 = (i & 15) * 4;
            float4 v = *(float4*)&sC[r * 68 + c4];
            *(float4*)&g_iin[(size_t)(m0 + r) * NHID + n0 + c4] = v;
        }
    }
}

// epilogue needs 128*68*4 = 34816 B of smem; allocate max(pipeline, epilogue)
#define SMEM_ALLOC 34816

// ---------------- phase 2: recurrence (unchanged from R16) ------------------
__global__ void __launch_bounds__(128) snn_seq(const float* __restrict__ wout,
                                               float* __restrict__ out) {
    __shared__ float s_wout[NOUT * NHID];
    __shared__ unsigned s_mask[16];
    __shared__ int   s_list[2][NHID];
    __shared__ int   s_cnt;
    __shared__ float s_iout[NOUT];

    const int b = blockIdx.x;
    const int t = threadIdx.x;
    const int w = t >> 5;
    const int lane = t & 31;

    for (int i = t; i < NOUT * NHID; i += 128) s_wout[i] = wout[i];
    if (t == 0) s_cnt = 0;

    float v1[4] = {0.f, 0.f, 0.f, 0.f};
    float a1[4] = {0.f, 0.f, 0.f, 0.f};
    float sp[4] = {0.f, 0.f, 0.f, 0.f};
    float v_out = 0.f, acc_out = 0.f;

    const float* iin_b = &g_iin[(size_t)b * TSTEPS * NHID];
    float cur[4];
#pragma unroll
    for (int g = 0; g < 4; g++) cur[g] = __ldg(&iin_b[g * 128 + t]);

    __syncthreads();

    const uint2* wp = g_wrecP;

    for (int ts = 0; ts < TSTEPS; ts++) {
        const int wb = ts & 1;
        const int cnt = s_cnt;
        const int* lst = s_list[wb ^ 1];

        float r[4] = {0.f, 0.f, 0.f, 0.f};
        int k = 0;
        for (; k + 8 <= cnt; k += 8) {
            uint2 u[8];
#pragma unroll
            for (int q = 0; q < 8; q++)
                u[q] = __ldg(&wp[(size_t)lst[k + q] * 128 + t]);
#pragma unroll
            for (int q = 0; q < 8; q++) {
                float2 f0 = __half22float2(*(__half2*)&u[q].x);
                float2 f1 = __half22float2(*(__half2*)&u[q].y);
                r[0] += f0.x; r[1] += f0.y; r[2] += f1.x; r[3] += f1.y;
            }
        }
        for (; k < cnt; k++) {
            uint2 u = __ldg(&wp[(size_t)lst[k] * 128 + t]);
            float2 f0 = __half22float2(*(__half2*)&u.x);
            float2 f1 = __half22float2(*(__half2*)&u.y);
            r[0] += f0.x; r[1] += f0.y; r[2] += f1.x; r[3] += f1.y;
        }

        float nxt[4] = {0.f, 0.f, 0.f, 0.f};
        if (ts + 1 < TSTEPS) {
#pragma unroll
            for (int g = 0; g < 4; g++)
                nxt[g] = __ldg(&iin_b[(size_t)(ts + 1) * NHID + g * 128 + t]);
        }

        float sn[4];
        unsigned m[4];
#pragma unroll
        for (int g = 0; g < 4; g++) {
            const float i1 = cur[g] + r[g];
            v1[g] = 0.95f * v1[g] + 0.05f * i1 - sp[g];
            a1[g] = 0.85f * a1[g] + 0.15f * sp[g];
            sn[g] = (v1[g] > 1.0f + 0.05f * a1[g]) ? 1.f : 0.f;
            m[g] = __ballot_sync(0xffffffffu, sn[g] > 0.f);
        }
        if (lane == 0) {
#pragma unroll
            for (int g = 0; g < 4; g++) s_mask[g * 4 + w] = m[g];
        }

        __syncthreads();

        int pre[4];
        int run = 0;
#pragma unroll
        for (int idx = 0; idx < 16; idx++) {
            int pc = __popc(s_mask[idx]);
#pragma unroll
            for (int g = 0; g < 4; g++)
                if (idx == g * 4 + w) pre[g] = run;
            run += pc;
        }
#pragma unroll
        for (int g = 0; g < 4; g++) {
            if (sn[g] > 0.f) {
                int pos = pre[g] + __popc(m[g] & ((1u << lane) - 1u));
                s_list[wb][pos] = g * 128 + w * 32 + lane;
            }
        }
        if (t == 0) s_cnt = run;

        for (int o = w; o < NOUT; o += 4) {
            float p = 0.f;
            const float* wrow = &s_wout[o * NHID];
#pragma unroll
            for (int idx = 0; idx < 16; idx++) {
                unsigned mm = s_mask[idx];
                if ((mm >> lane) & 1u)
                    p += wrow[(idx >> 2) * 128 + (idx & 3) * 32 + lane];
            }
#pragma unroll
            for (int off = 16; off > 0; off >>= 1)
                p += __shfl_down_sync(0xffffffffu, p, off);
            if (lane == 0) s_iout[o] = p;
        }

        __syncthreads();

        if (t < NOUT) {
            v_out = 0.9f * v_out + s_iout[t];
            const float s_o = (v_out > 1.0f) ? 1.f : 0.f;
            v_out = v_out - 1.0f * s_o;
            acc_out += v_out;
        }

#pragma unroll
        for (int g = 0; g < 4; g++) { sp[g] = sn[g]; cur[g] = nxt[g]; }
    }

    if (t < NOUT) out[b * NOUT + t] = acc_out * (1.0f / (float)TSTEPS);
}

// ---------------- launch -----------------------------------------------------
extern "C" void kernel_launch(void* const* d_in, const int* in_sizes, int n_in,
                              void* d_out, int out_size) {
    const float* x    = (const float*)d_in[0];
    const float* wkan = (const float*)d_in[1];
    const float* d1   = (const float*)d_in[2];
    const float* d2   = (const float*)d_in[3];
    const float* d3   = (const float*)d_in[4];
    const float* wrec = (const float*)d_in[5];
    const float* wout = (const float*)d_in[6];
    float* out = (float*)d_out;

    cudaFuncSetAttribute(gemm_mma, cudaFuncAttributeMaxDynamicSharedMemorySize, SMEM_ALLOC);

    prep_A<<<(MROWS * (VPITCH / 4) + 255) / 256, 256>>>(x);
    prep_B<<<(NHID * (VPITCH / 4) + 255) / 256, 256>>>(wkan, d1, d2, d3);
    prep_wrec<<<(NHID * 128 + 255) / 256, 256>>>(wrec);

    dim3 grid(NHID / BN, MROWS / BM);   // (8, 500)
    gemm_mma<<<grid, 128, SMEM_ALLOC>>>();

    snn_seq<<<BATCH, 128>>>(wout, out);
}